// round 15
// baseline (speedup 1.0000x reference)
#include <cuda_runtime.h>
#include <cuda_fp16.h>
#include <cstdint>
#include <math.h>

#define BATCH  2
#define TSEQ   2048
#define BT     (BATCH*TSEQ)   // 4096
#define DMODEL 1024
#define NHEAD  16
#define DHEAD  64
#define VOCAB  32000

// ---------------- scratch (device globals; referenced ONLY from device code) ----
__device__ __align__(16) int   g_cnt[VOCAB];
__device__ __align__(16) float g_m[3][DMODEL];
__device__ __align__(16) float g_gate[BT*DMODEL];                       // sigmoid(r)
__device__ __align__(16) __half g_ah[3][BT*DMODEL];                     // A fp16 (mode3 reuses [0])
__device__ __align__(16) __half g_al1[BT*DMODEL];                       // A lo (k-GEMM only)
__device__ __align__(16) __half g_wh[4][DMODEL*DMODEL];                 // W fp16 (all 4)
__device__ __align__(16) __half g_wl[DMODEL*DMODEL];                    // W lo (k-GEMM only)
__device__ __align__(16) __half g_qs[BT*DMODEL];                        // q*0.125 (fp16)
__device__ __align__(16) __half g_kb[BT*DMODEL];                        // k (binary)
__device__ __align__(16) __half g_vf[BATCH*NHEAD*DHEAD*TSEQ];           // V^T (single fp16)

// ---------------- helpers ----------------
__device__ __forceinline__ void h_split(float x, __half& h, __half& l) {
    h = __float2half_rn(x);
    l = __float2half_rn(x - __half2float(h));
}
__device__ __forceinline__ uint32_t pack2h(float x, float y) {
    __half2 hh = __floats2half2_rn(x, y);
    return *(uint32_t*)&hh;
}
__device__ __forceinline__ uint32_t smem_u32(const void* p) {
    uint32_t a;
    asm("{ .reg .u64 t; cvta.to.shared.u64 t, %1; cvt.u32.u64 %0, t; }" : "=r"(a) : "l"(p));
    return a;
}
__device__ __forceinline__ float exps4(float s) {
    return exp2f(fmaf(s, 1.44269504f, -5.77078016f));
}
#define U32(p) (*reinterpret_cast<const uint32_t*>(p))
#define CP16(dst, src) asm volatile("cp.async.cg.shared.global [%0], [%1], 16;" :: "r"(dst), "l"(src))
#define CPCOMMIT()     asm volatile("cp.async.commit_group;")
#define CPWAIT0()      asm volatile("cp.async.wait_group 0;")

#define MMA_F16(c, a0, a1, a2, a3, b0, b1)                                      \
    asm volatile(                                                               \
        "mma.sync.aligned.m16n8k16.row.col.f32.f16.f16.f32 "                    \
        "{%0,%1,%2,%3}, {%4,%5,%6,%7}, {%8,%9}, {%0,%1,%2,%3};"                 \
        : "+f"((c)[0]), "+f"((c)[1]), "+f"((c)[2]), "+f"((c)[3])                \
        : "r"(a0), "r"(a1), "r"(a2), "r"(a3), "r"(b0), "r"(b1))

// ---------------- kWTA: histogram + top-5 + gains ----------------
__global__ void zero_cnt_kernel() {
    int i = blockIdx.x * blockDim.x + threadIdx.x;
    if (i < VOCAB) g_cnt[i] = 0;
}
__global__ void hist_kernel(const int* __restrict__ tok) {
    int i = blockIdx.x * blockDim.x + threadIdx.x;
    atomicAdd(&g_cnt[tok[i]], 1);
}
__global__ void topk_gains_kernel(const float* __restrict__ tmr,
                                  const float* __restrict__ tmk,
                                  const float* __restrict__ tmv) {
    __shared__ long long skey[256];
    __shared__ int sel[5];
    int tid = threadIdx.x;
    for (int it = 0; it < 5; it++) {
        long long best = -1;
        for (int i = tid; i < VOCAB; i += 256) {
            bool ex = false;
            for (int j = 0; j < it; j++) if (sel[j] == i) ex = true;
            if (ex) continue;
            long long key = (((long long)g_cnt[i]) << 16) | (long long)(VOCAB - 1 - i);
            if (key > best) best = key;
        }
        skey[tid] = best;
        __syncthreads();
        for (int s = 128; s > 0; s >>= 1) {
            if (tid < s && skey[tid + s] > skey[tid]) skey[tid] = skey[tid + s];
            __syncthreads();
        }
        if (tid == 0) sel[it] = VOCAB - 1 - (int)(skey[0] & 0xFFFFLL);
        __syncthreads();
    }
    for (int d = tid; d < DMODEL; d += 256) {
        float g = (g_cnt[d] > 0) ? 0.6f : 1.0f;
        #pragma unroll
        for (int j = 0; j < 5; j++) if (sel[j] == d) g = 1.5f;
        g_m[0][d] = tmr[d] * g;
        g_m[1][d] = tmk[d] * g;
        g_m[2][d] = tmv[d] * g;
    }
}

// ---------------- prep: W fp16 x4; W lo only for Wk ----------------
__global__ void split_w_all(const float* __restrict__ W0, const float* __restrict__ W1,
                            const float* __restrict__ W2, const float* __restrict__ W3) {
    int i = blockIdx.x * 256 + threadIdx.x;
    const float* Ws[4] = {W0, W1, W2, W3};
    #pragma unroll
    for (int m = 0; m < 4; m++) {
        __half h, l;
        h_split(Ws[m][i], h, l);
        g_wh[m][i] = h;
        if (m == 1) g_wl[i] = l;
    }
}

// ---------------- prep: 3 mixed inputs (A-lo only for k path) ----------------
__global__ void prep_x012(const float* __restrict__ X) {
    int i = blockIdx.x * 256 + threadIdx.x;
    int t = i >> 10, d = i & (DMODEL - 1);
    float xv = X[i];
    float pv = ((t & (TSEQ - 1)) != 0) ? X[i - DMODEL] : 0.f;
    #pragma unroll
    for (int m = 0; m < 3; m++) {
        float mm = g_m[m][d];
        float a = mm * xv + (1.f - mm) * pv;
        __half h, l;
        h_split(a, h, l);
        g_ah[m][i] = h;
        if (m == 1) g_al1[i] = l;
    }
}

// ======== 1-term fp16 GEMM, CTA 128x256, warp tile 64x64, CH=32 ===============
// 8 warps (2 M-bands x 4 N-bands). Dynamic smem 61,440 B: sA 2x[128x40],
// sW 2x[256x40]. Double-buffered cp.async. mode = z ? modeB : modeA.
// Epilogues: 0 -> gate + q*0.125 ; 2 -> V^T fp16 ; 3 -> out + bias.
#define SBW 40
#define ABYTES (128 * SBW * 2)   // one A stage
#define WBYTES (256 * SBW * 2)   // one W stage
__global__ __launch_bounds__(256, 1)
void gemm_256(int modeA, int modeB, const float* __restrict__ bias, float* __restrict__ Cout)
{
    extern __shared__ __half sm[];
    __half* sA = sm;                       // 2 stages x 128 x SBW
    __half* sW = sm + 2 * 128 * SBW;       // 2 stages x 256 x SBW

    const int mode = blockIdx.z ? modeB : modeA;
    const __half* __restrict__ Ah = g_ah[mode == 3 ? 0 : mode];
    const __half* __restrict__ Wh = g_wh[mode];

    const int tid  = threadIdx.x;
    const int wid  = tid >> 5, lane = tid & 31;
    const int wr   = wid & 1,  wc   = wid >> 1;       // 64-row band / 64-col band
    const int qrow = lane >> 2, qc = lane & 3;
    const int bm = blockIdx.y * 128, bn = blockIdx.x * 256;

    // loaders: A -> 128 rows x 32 halves (2 CP16/thread), W -> 256 rows x 32 (4 CP16)
    const int alr = tid >> 1, acg = (tid & 1) * 16;
    const __half* pA = Ah + (size_t)(bm + alr) * DMODEL + acg;
    const __half* pW = Wh + (size_t)(bn + tid) * DMODEL;
    const uint32_t aB = smem_u32(sA) + (alr * SBW + acg) * 2;
    const uint32_t wB = smem_u32(sW) + (tid * SBW) * 2;

    float acc[4][8][4];
    #pragma unroll
    for (int mi = 0; mi < 4; mi++)
        #pragma unroll
        for (int ni = 0; ni < 8; ni++)
            #pragma unroll
            for (int e = 0; e < 4; e++) acc[mi][ni][e] = 0.f;

    CP16(aB, pA); CP16(aB + 16, pA + 8);
    CP16(wB, pW); CP16(wB + 16, pW + 8); CP16(wB + 32, pW + 16); CP16(wB + 48, pW + 24);
    CPCOMMIT();

    for (int c = 0; c < DMODEL / 32; c++) {
        CPWAIT0();
        __syncthreads();
        if (c + 1 < DMODEL / 32) {
            const uint32_t soA = ((c + 1) & 1) * ABYTES;
            const uint32_t soW = ((c + 1) & 1) * WBYTES;
            const int go = (c + 1) * 32;
            CP16(aB + soA, pA + go); CP16(aB + soA + 16, pA + go + 8);
            CP16(wB + soW, pW + go);      CP16(wB + soW + 16, pW + go + 8);
            CP16(wB + soW + 32, pW + go + 16); CP16(wB + soW + 48, pW + go + 24);
            CPCOMMIT();
        }
        const __half* cA = sA + (c & 1) * 128 * SBW;
        const __half* cW = sW + (c & 1) * 256 * SBW;

        #pragma unroll
        for (int ks = 0; ks < 2; ks++) {
            const int k0 = ks * 16 + 2 * qc;
            uint32_t bh[8][2];
            #pragma unroll
            for (int ni = 0; ni < 8; ni++) {
                const int off = (wc * 64 + ni * 8 + qrow) * SBW + k0;
                bh[ni][0] = U32(cW + off); bh[ni][1] = U32(cW + off + 8);
            }
            #pragma unroll
            for (int mi = 0; mi < 4; mi++) {
                const int off = (wr * 64 + mi * 16 + qrow) * SBW + k0;
                uint32_t a0 = U32(cA + off),     a1 = U32(cA + off + 8 * SBW);
                uint32_t a2 = U32(cA + off + 8), a3 = U32(cA + off + 8 * SBW + 8);
                #pragma unroll
                for (int ni = 0; ni < 8; ni++)
                    MMA_F16(acc[mi][ni], a0, a1, a2, a3, bh[ni][0], bh[ni][1]);
            }
        }
    }

    #pragma unroll
    for (int mi = 0; mi < 4; mi++) {
        const int row0 = bm + wr * 64 + mi * 16 + qrow;
        #pragma unroll
        for (int ni = 0; ni < 8; ni++) {
            const int col = bn + wc * 64 + ni * 8 + 2 * qc;
            float d0 = acc[mi][ni][0], d1 = acc[mi][ni][1];
            float d2 = acc[mi][ni][2], d3 = acc[mi][ni][3];
            if (mode == 0) {
                *(float2*)(g_gate + (size_t)row0 * DMODEL + col) =
                    make_float2(1.f / (1.f + __expf(-d0)), 1.f / (1.f + __expf(-d1)));
                *(float2*)(g_gate + (size_t)(row0 + 8) * DMODEL + col) =
                    make_float2(1.f / (1.f + __expf(-d2)), 1.f / (1.f + __expf(-d3)));
                *(uint32_t*)(g_qs + (size_t)row0 * DMODEL + col)       = pack2h(d0 * 0.125f, d1 * 0.125f);
                *(uint32_t*)(g_qs + (size_t)(row0 + 8) * DMODEL + col) = pack2h(d2 * 0.125f, d3 * 0.125f);
            } else if (mode == 2) {
                const int b  = row0 >> 11, tl = row0 & (TSEQ - 1);
                const int hh = col >> 6,  dd = col & (DHEAD - 1);
                const size_t base = ((size_t)(b * NHEAD + hh)) * DHEAD;
                g_vf[(base + dd) * TSEQ + tl]         = __float2half(d0);
                g_vf[(base + dd + 1) * TSEQ + tl]     = __float2half(d1);
                g_vf[(base + dd) * TSEQ + tl + 8]     = __float2half(d2);
                g_vf[(base + dd + 1) * TSEQ + tl + 8] = __float2half(d3);
            } else {
                float b0 = bias[col], b1 = bias[col + 1];
                *(float2*)(Cout + (size_t)row0 * DMODEL + col)       = make_float2(d0 + b0, d1 + b1);
                *(float2*)(Cout + (size_t)(row0 + 8) * DMODEL + col) = make_float2(d2 + b0, d3 + b1);
            }
        }
    }
}

// ================= 3-term fp16 GEMM (mode 1: k, spike epilogue) ================
// Known-good R13 kernel: precision of the spike threshold REQUIRES 3 terms.
#define CH3  16
#define SB3  24
#define STG3 (128 * SB3 * 2)
__global__ __launch_bounds__(256)
void gemm_3t()
{
    const __half* __restrict__ Ah = g_ah[1];
    const __half* __restrict__ Al = g_al1;
    const __half* __restrict__ Wh = g_wh[1];
    const __half* __restrict__ Wl = g_wl;

    __shared__ __align__(16) __half sAh[2][128 * SB3], sAl[2][128 * SB3];
    __shared__ __align__(16) __half sWh[2][128 * SB3], sWl[2][128 * SB3];

    const int tid  = threadIdx.x;
    const int wid  = tid >> 5, lane = tid & 31;
    const int wr   = wid & 1,  wc   = wid >> 1;
    const int qrow = lane >> 2, qc = lane & 3;
    const int bm = blockIdx.y * 128, bn = blockIdx.x * 128;
    const int lr = tid >> 1, cg = (tid & 1) * 8;

    const __half* pAh = Ah + (size_t)(bm + lr) * DMODEL + cg;
    const __half* pAl = Al + (size_t)(bm + lr) * DMODEL + cg;
    const __half* pWh = Wh + (size_t)(bn + lr) * DMODEL + cg;
    const __half* pWl = Wl + (size_t)(bn + lr) * DMODEL + cg;
    const uint32_t dAh = smem_u32(sAh) + (lr * SB3 + cg) * 2;
    const uint32_t dAl = smem_u32(sAl) + (lr * SB3 + cg) * 2;
    const uint32_t dWh = smem_u32(sWh) + (lr * SB3 + cg) * 2;
    const uint32_t dWl = smem_u32(sWl) + (lr * SB3 + cg) * 2;

    float acc[4][4][4];
    #pragma unroll
    for (int mi = 0; mi < 4; mi++)
        #pragma unroll
        for (int ni = 0; ni < 4; ni++)
            #pragma unroll
            for (int e = 0; e < 4; e++) acc[mi][ni][e] = 0.f;

    CP16(dAh, pAh); CP16(dAl, pAl); CP16(dWh, pWh); CP16(dWl, pWl);
    CPCOMMIT();

    for (int c = 0; c < DMODEL / CH3; c++) {
        CPWAIT0();
        __syncthreads();
        if (c + 1 < DMODEL / CH3) {
            const uint32_t so = ((c + 1) & 1) * STG3;
            const int go = (c + 1) * CH3;
            CP16(dAh + so, pAh + go); CP16(dAl + so, pAl + go);
            CP16(dWh + so, pWh + go); CP16(dWl + so, pWl + go);
            CPCOMMIT();
        }
        const __half* cAh = sAh[c & 1];
        const __half* cAl = sAl[c & 1];
        const __half* cWh = sWh[c & 1];
        const __half* cWl = sWl[c & 1];

        const int k0 = 2 * qc;
        uint32_t bh[4][2], bl[4][2];
        #pragma unroll
        for (int ni = 0; ni < 4; ni++) {
            const int off = (wc * 32 + ni * 8 + qrow) * SB3 + k0;
            bh[ni][0] = U32(cWh + off); bh[ni][1] = U32(cWh + off + 8);
            bl[ni][0] = U32(cWl + off); bl[ni][1] = U32(cWl + off + 8);
        }
        #pragma unroll
        for (int mi = 0; mi < 4; mi++) {
            const int off = (wr * 64 + mi * 16 + qrow) * SB3 + k0;
            uint32_t ah0 = U32(cAh + off),     ah1 = U32(cAh + off + 8 * SB3);
            uint32_t ah2 = U32(cAh + off + 8), ah3 = U32(cAh + off + 8 * SB3 + 8);
            uint32_t al0 = U32(cAl + off),     al1 = U32(cAl + off + 8 * SB3);
            uint32_t al2 = U32(cAl + off + 8), al3 = U32(cAl + off + 8 * SB3 + 8);
            #pragma unroll
            for (int ni = 0; ni < 4; ni++) {
                MMA_F16(acc[mi][ni], al0, al1, al2, al3, bh[ni][0], bh[ni][1]);
                MMA_F16(acc[mi][ni], ah0, ah1, ah2, ah3, bl[ni][0], bl[ni][1]);
                MMA_F16(acc[mi][ni], ah0, ah1, ah2, ah3, bh[ni][0], bh[ni][1]);
            }
        }
    }

    #pragma unroll
    for (int mi = 0; mi < 4; mi++) {
        const int row0 = bm + wr * 64 + mi * 16 + qrow;
        #pragma unroll
        for (int ni = 0; ni < 4; ni++) {
            const int col = bn + wc * 32 + ni * 8 + 2 * qc;
            *(uint32_t*)(g_kb + (size_t)row0 * DMODEL + col) =
                pack2h((acc[mi][ni][0] > 0.5f) ? 1.f : 0.f,
                       (acc[mi][ni][1] > 0.5f) ? 1.f : 0.f);
            *(uint32_t*)(g_kb + (size_t)(row0 + 8) * DMODEL + col) =
                pack2h((acc[mi][ni][2] > 0.5f) ? 1.f : 0.f,
                       (acc[mi][ni][3] > 0.5f) ? 1.f : 0.f);
        }
    }
}

// ---------------- flash attention: no online softmax (bounded scores) ----------
#define KS 72
#define VS 40
__global__ __launch_bounds__(256)
void attn_f16()
{
    __shared__ __align__(16) __half sKb[2][32 * KS];
    __shared__ __align__(16) __half sVf[2][64 * VS];

    const int tid = threadIdx.x, warp = tid >> 5, lane = tid & 31;
    const int qr = lane >> 2, qc = lane & 3;
    const int b = blockIdx.z, h = blockIdx.y;
    const int qb = blockIdx.x * 128 + warp * 16;

    const int kkey = tid >> 3, kdg = (tid & 7) * 8;
    const int vd = tid >> 2,   vkg = (tid & 3) * 8;
    const size_t vbase = ((size_t)(b * NHEAD + h)) * DHEAD * TSEQ;
    const __half* gK  = g_kb + (size_t)(b * TSEQ + kkey) * DMODEL + h * DHEAD + kdg;
    const __half* gVf = g_vf + vbase + (size_t)vd * TSEQ + vkg;
    const uint32_t sKa  = smem_u32(sKb) + (kkey * KS + kdg) * 2;
    const uint32_t sVfa = smem_u32(sVf) + (vd * VS + vkg) * 2;
    const uint32_t KBUF = 32 * KS * 2, VBUF = 64 * VS * 2;

    uint32_t qf[4][4];
    {
        const size_t r0 = (size_t)(b * TSEQ + qb + qr) * DMODEL + h * DHEAD;
        const size_t r1 = r0 + (size_t)8 * DMODEL;
        #pragma unroll
        for (int kc = 0; kc < 4; kc++) {
            const int cc = kc * 16 + 2 * qc;
            qf[kc][0] = U32(g_qs + r0 + cc);     qf[kc][1] = U32(g_qs + r1 + cc);
            qf[kc][2] = U32(g_qs + r0 + cc + 8); qf[kc][3] = U32(g_qs + r1 + cc + 8);
        }
    }

    float o[8][4];
    #pragma unroll
    for (int nd = 0; nd < 8; nd++)
        #pragma unroll
        for (int e = 0; e < 4; e++) o[nd][e] = 0.f;
    float l0 = 0.f, l1 = 0.f;

    CP16(sKa, gK);
    CP16(sVfa, gVf);
    CPCOMMIT();

    int buf = 0;
    for (int kt = 0; kt < TSEQ; kt += 32) {
        CPWAIT0();
        __syncthreads();
        if (kt + 32 < TSEQ) {
            const int nb = buf ^ 1;
            CP16(sKa + nb * KBUF, gK + (kt + 32) * DMODEL);
            CP16(sVfa + nb * VBUF, gVf + kt + 32);
            CPCOMMIT();
        }
        const __half* Kb = sKb[buf];
        const __half* Vf = sVf[buf];

        float s[4][4];
        #pragma unroll
        for (int nt = 0; nt < 4; nt++) {
            #pragma unroll
            for (int e = 0; e < 4; e++) s[nt][e] = 0.f;
            #pragma unroll
            for (int kc = 0; kc < 4; kc++) {
                const int off = (nt * 8 + qr) * KS + kc * 16 + 2 * qc;
                uint32_t b0 = U32(Kb + off), b1 = U32(Kb + off + 8);
                MMA_F16(s[nt], qf[kc][0], qf[kc][1], qf[kc][2], qf[kc][3], b0, b1);
            }
        }

        #pragma unroll
        for (int nt = 0; nt < 4; nt++) {
            s[nt][0] = exps4(s[nt][0]);
            s[nt][1] = exps4(s[nt][1]);
            s[nt][2] = exps4(s[nt][2]);
            s[nt][3] = exps4(s[nt][3]);
            l0 += s[nt][0] + s[nt][1];
            l1 += s[nt][2] + s[nt][3];
        }

        #pragma unroll
        for (int kc = 0; kc < 2; kc++) {
            uint32_t a0 = pack2h(s[2*kc][0],     s[2*kc][1]);
            uint32_t a1 = pack2h(s[2*kc][2],     s[2*kc][3]);
            uint32_t a2 = pack2h(s[2*kc + 1][0], s[2*kc + 1][1]);
            uint32_t a3 = pack2h(s[2*kc + 1][2], s[2*kc + 1][3]);
            const int k0 = kc * 16 + 2 * qc;
            #pragma unroll
            for (int nd = 0; nd < 8; nd++) {
                const int off = (nd * 8 + qr) * VS + k0;
                uint32_t bh0 = U32(Vf + off), bh1 = U32(Vf + off + 8);
                MMA_F16(o[nd], a0, a1, a2, a3, bh0, bh1);
            }
        }
        buf ^= 1;
    }

    l0 += __shfl_xor_sync(0xffffffffu, l0, 1);
    l0 += __shfl_xor_sync(0xffffffffu, l0, 2);
    l1 += __shfl_xor_sync(0xffffffffu, l1, 1);
    l1 += __shfl_xor_sync(0xffffffffu, l1, 2);

    const float inv0 = 1.f / l0, inv1 = 1.f / l1;
    const size_t r0 = (size_t)(b * TSEQ + qb + qr) * DMODEL + h * DHEAD;
    const size_t r1 = r0 + (size_t)8 * DMODEL;
    #pragma unroll
    for (int nd = 0; nd < 8; nd++) {
        const int cc = nd * 8 + 2 * qc;
        float2 gt0 = *(const float2*)(g_gate + r0 + cc);
        float2 gt1 = *(const float2*)(g_gate + r1 + cc);
        *(uint32_t*)(g_ah[0] + r0 + cc) =
            pack2h(o[nd][0] * inv0 * gt0.x, o[nd][1] * inv0 * gt0.y);
        *(uint32_t*)(g_ah[0] + r1 + cc) =
            pack2h(o[nd][2] * inv1 * gt1.x, o[nd][3] * inv1 * gt1.y);
    }
}

// ---------------- launch (only harness pointers cross the boundary) ----------
#define GEMM256_SMEM (2 * (128 + 256) * SBW * 2)   // 61,440 bytes
extern "C" void kernel_launch(void* const* d_in, const int* in_sizes, int n_in,
                              void* d_out, int out_size)
{
    const float* x   = (const float*)d_in[0];
    const int*   tok = (const int*)  d_in[1];
    const float* Wr  = (const float*)d_in[2];
    const float* Wk  = (const float*)d_in[3];
    const float* Wv  = (const float*)d_in[4];
    const float* Wo  = (const float*)d_in[5];
    const float* bo  = (const float*)d_in[6];
    const float* tmk = (const float*)d_in[7];
    const float* tmv = (const float*)d_in[8];
    const float* tmr = (const float*)d_in[9];
    float* out = (float*)d_out;

    static bool attr_done = false;
    if (!attr_done) {
        cudaFuncSetAttribute(gemm_256, cudaFuncAttributeMaxDynamicSharedMemorySize,
                             GEMM256_SMEM);
        attr_done = true;
    }

    zero_cnt_kernel<<<(VOCAB + 255) / 256, 256>>>();
    hist_kernel<<<BT / 256, 256>>>(tok);
    topk_gains_kernel<<<1, 256>>>(tmr, tmk, tmv);

    split_w_all<<<(DMODEL * DMODEL) / 256, 256>>>(Wr, Wk, Wv, Wo);
    prep_x012<<<(BT * DMODEL) / 256, 256>>>(x);

    gemm_256<<<dim3(DMODEL / 256, BT / 128, 2), 256, GEMM256_SMEM>>>(0, 2, nullptr, nullptr); // r, v
    gemm_3t<<<dim3(DMODEL / 128, BT / 128), 256>>>();                                         // k

    attn_f16<<<dim3(TSEQ / 128, NHEAD, BATCH), 256>>>();

    gemm_256<<<dim3(DMODEL / 256, BT / 128, 1), 256, GEMM256_SMEM>>>(3, 3, bo, out);          // out
}

// round 17
// speedup vs baseline: 1.0390x; 1.0390x over previous
#include <cuda_runtime.h>
#include <cuda_fp16.h>
#include <cstdint>
#include <math.h>

#define BATCH  2
#define TSEQ   2048
#define BT     (BATCH*TSEQ)   // 4096
#define DMODEL 1024
#define NHEAD  16
#define DHEAD  64
#define VOCAB  32000
#define MAXFIX 262144
#define EPS_K  1.5e-3f

// ---------------- scratch (device globals; referenced ONLY from device code) ----
__device__ __align__(16) int   g_cnt[VOCAB];
__device__ int  g_nfix;
__device__ __align__(16) int2  g_fix[MAXFIX];
__device__ __align__(16) float g_m[3][DMODEL];
__device__ __align__(16) float g_gate[BT*DMODEL];                       // sigmoid(r)
__device__ __align__(16) __half g_ah[3][BT*DMODEL];                     // A fp16 (mode3 reuses [0])
__device__ __align__(16) __half g_wh[4][DMODEL*DMODEL];                 // W fp16
__device__ __align__(16) __half g_qs[BT*DMODEL];                        // q*0.125 (fp16)
__device__ __align__(16) __half g_kb[BT*DMODEL];                        // k (binary)
__device__ __align__(16) __half g_vf[BATCH*NHEAD*DHEAD*TSEQ];           // V^T (fp16)

// ---------------- helpers ----------------
__device__ __forceinline__ uint32_t pack2h(float x, float y) {
    __half2 hh = __floats2half2_rn(x, y);
    return *(uint32_t*)&hh;
}
__device__ __forceinline__ uint32_t smem_u32(const void* p) {
    uint32_t a;
    asm("{ .reg .u64 t; cvta.to.shared.u64 t, %1; cvt.u32.u64 %0, t; }" : "=r"(a) : "l"(p));
    return a;
}
__device__ __forceinline__ float exps4(float s) {
    return exp2f(fmaf(s, 1.44269504f, -5.77078016f));
}
#define U32(p) (*reinterpret_cast<const uint32_t*>(p))
#define CP16(dst, src) asm volatile("cp.async.cg.shared.global [%0], [%1], 16;" :: "r"(dst), "l"(src))
#define CPCOMMIT()     asm volatile("cp.async.commit_group;")
#define CPWAIT0()      asm volatile("cp.async.wait_group 0;")

#define MMA_F16(c, a0, a1, a2, a3, b0, b1)                                      \
    asm volatile(                                                               \
        "mma.sync.aligned.m16n8k16.row.col.f32.f16.f16.f32 "                    \
        "{%0,%1,%2,%3}, {%4,%5,%6,%7}, {%8,%9}, {%0,%1,%2,%3};"                 \
        : "+f"((c)[0]), "+f"((c)[1]), "+f"((c)[2]), "+f"((c)[3])                \
        : "r"(a0), "r"(a1), "r"(a2), "r"(a3), "r"(b0), "r"(b1))

// ---------------- kWTA: histogram + top-5 + gains ----------------
__global__ void zero_cnt_kernel() {
    int i = blockIdx.x * blockDim.x + threadIdx.x;
    if (i < VOCAB) g_cnt[i] = 0;
    if (i == 0) g_nfix = 0;
}
__global__ void hist_kernel(const int* __restrict__ tok) {
    int i = blockIdx.x * blockDim.x + threadIdx.x;
    atomicAdd(&g_cnt[tok[i]], 1);
}
__global__ void topk_gains_kernel(const float* __restrict__ tmr,
                                  const float* __restrict__ tmk,
                                  const float* __restrict__ tmv) {
    __shared__ long long skey[256];
    __shared__ int sel[5];
    int tid = threadIdx.x;
    for (int it = 0; it < 5; it++) {
        long long best = -1;
        for (int i = tid; i < VOCAB; i += 256) {
            bool ex = false;
            for (int j = 0; j < it; j++) if (sel[j] == i) ex = true;
            if (ex) continue;
            long long key = (((long long)g_cnt[i]) << 16) | (long long)(VOCAB - 1 - i);
            if (key > best) best = key;
        }
        skey[tid] = best;
        __syncthreads();
        for (int s = 128; s > 0; s >>= 1) {
            if (tid < s && skey[tid + s] > skey[tid]) skey[tid] = skey[tid + s];
            __syncthreads();
        }
        if (tid == 0) sel[it] = VOCAB - 1 - (int)(skey[0] & 0xFFFFLL);
        __syncthreads();
    }
    for (int d = tid; d < DMODEL; d += 256) {
        float g = (g_cnt[d] > 0) ? 0.6f : 1.0f;
        #pragma unroll
        for (int j = 0; j < 5; j++) if (sel[j] == d) g = 1.5f;
        g_m[0][d] = tmr[d] * g;
        g_m[1][d] = tmk[d] * g;
        g_m[2][d] = tmv[d] * g;
    }
}

// ---------------- prep: all 4 W -> fp16 ----------------
__global__ void split_w_all(const float* __restrict__ W0, const float* __restrict__ W1,
                            const float* __restrict__ W2, const float* __restrict__ W3) {
    int i = blockIdx.x * 256 + threadIdx.x;
    g_wh[0][i] = __float2half_rn(W0[i]);
    g_wh[1][i] = __float2half_rn(W1[i]);
    g_wh[2][i] = __float2half_rn(W2[i]);
    g_wh[3][i] = __float2half_rn(W3[i]);
}

// ---------------- prep: 3 mixed inputs (x read once) ----------------
__global__ void prep_x012(const float* __restrict__ X) {
    int i = blockIdx.x * 256 + threadIdx.x;
    int t = i >> 10, d = i & (DMODEL - 1);
    float xv = X[i];
    float pv = ((t & (TSEQ - 1)) != 0) ? X[i - DMODEL] : 0.f;
    #pragma unroll
    for (int m = 0; m < 3; m++) {
        float mm = g_m[m][d];
        g_ah[m][i] = __float2half_rn(mm * xv + (1.f - mm) * pv);
    }
}

// ================= 1-term fp16 GEMM (all modes), K-chunk 32 ====================
// CTA 128x128, 8 warps (64x32 warp tile), double-buffered cp.async, 32 chunks.
// mode = mode_base + blockIdx.z. Epilogues:
//  0 -> gate + q*0.125 ; 1 -> spike -> g_kb, flag near-threshold to g_fix ;
//  2 -> g_vf transposed ; 3 -> Cout + bias.
#define CH1  32
#define SB1  40
#define STG1 (128 * SB1 * 2)
__global__ __launch_bounds__(256)
void gemm_1t(int mode_base, const float* __restrict__ bias, float* __restrict__ Cout)
{
    const int mode = mode_base + blockIdx.z;
    const __half* __restrict__ Ah = g_ah[mode == 3 ? 0 : mode];
    const __half* __restrict__ Wh = g_wh[mode];

    __shared__ __align__(16) __half sAh[2][128 * SB1], sWh[2][128 * SB1];

    const int tid  = threadIdx.x;
    const int wid  = tid >> 5, lane = tid & 31;
    const int wr   = wid & 1,  wc   = wid >> 1;
    const int qrow = lane >> 2, qc = lane & 3;
    const int bm = blockIdx.y * 128, bn = blockIdx.x * 128;
    const int lr = tid >> 1, cg = (tid & 1) * 16;

    const __half* pAh = Ah + (size_t)(bm + lr) * DMODEL + cg;
    const __half* pWh = Wh + (size_t)(bn + lr) * DMODEL + cg;
    const uint32_t dAh = smem_u32(sAh) + (lr * SB1 + cg) * 2;
    const uint32_t dWh = smem_u32(sWh) + (lr * SB1 + cg) * 2;

    float acc[4][4][4];
    #pragma unroll
    for (int mi = 0; mi < 4; mi++)
        #pragma unroll
        for (int ni = 0; ni < 4; ni++)
            #pragma unroll
            for (int e = 0; e < 4; e++) acc[mi][ni][e] = 0.f;

    CP16(dAh, pAh); CP16(dAh + 16, pAh + 8);
    CP16(dWh, pWh); CP16(dWh + 16, pWh + 8);
    CPCOMMIT();

    for (int c = 0; c < DMODEL / CH1; c++) {
        CPWAIT0();
        __syncthreads();
        if (c + 1 < DMODEL / CH1) {
            const uint32_t so = ((c + 1) & 1) * STG1;
            const int go = (c + 1) * CH1;
            CP16(dAh + so, pAh + go); CP16(dAh + so + 16, pAh + go + 8);
            CP16(dWh + so, pWh + go); CP16(dWh + so + 16, pWh + go + 8);
            CPCOMMIT();
        }
        const __half* cAh = sAh[c & 1];
        const __half* cWh = sWh[c & 1];

        #pragma unroll
        for (int ks = 0; ks < 2; ks++) {
            const int k0 = ks * 16 + 2 * qc;
            uint32_t bh[4][2];
            #pragma unroll
            for (int ni = 0; ni < 4; ni++) {
                const int off = (wc * 32 + ni * 8 + qrow) * SB1 + k0;
                bh[ni][0] = U32(cWh + off); bh[ni][1] = U32(cWh + off + 8);
            }
            #pragma unroll
            for (int mi = 0; mi < 4; mi++) {
                const int off = (wr * 64 + mi * 16 + qrow) * SB1 + k0;
                uint32_t a0 = U32(cAh + off),     a1 = U32(cAh + off + 8 * SB1);
                uint32_t a2 = U32(cAh + off + 8), a3 = U32(cAh + off + 8 * SB1 + 8);
                #pragma unroll
                for (int ni = 0; ni < 4; ni++)
                    MMA_F16(acc[mi][ni], a0, a1, a2, a3, bh[ni][0], bh[ni][1]);
            }
        }
    }

    #pragma unroll
    for (int mi = 0; mi < 4; mi++) {
        const int row0 = bm + wr * 64 + mi * 16 + qrow;
        #pragma unroll
        for (int ni = 0; ni < 4; ni++) {
            const int col = bn + wc * 32 + ni * 8 + 2 * qc;
            float d0 = acc[mi][ni][0], d1 = acc[mi][ni][1];
            float d2 = acc[mi][ni][2], d3 = acc[mi][ni][3];
            if (mode == 0) {
                *(float2*)(g_gate + (size_t)row0 * DMODEL + col) =
                    make_float2(1.f / (1.f + __expf(-d0)), 1.f / (1.f + __expf(-d1)));
                *(float2*)(g_gate + (size_t)(row0 + 8) * DMODEL + col) =
                    make_float2(1.f / (1.f + __expf(-d2)), 1.f / (1.f + __expf(-d3)));
                *(uint32_t*)(g_qs + (size_t)row0 * DMODEL + col)       = pack2h(d0 * 0.125f, d1 * 0.125f);
                *(uint32_t*)(g_qs + (size_t)(row0 + 8) * DMODEL + col) = pack2h(d2 * 0.125f, d3 * 0.125f);
            } else if (mode == 1) {
                *(uint32_t*)(g_kb + (size_t)row0 * DMODEL + col) =
                    pack2h((d0 > 0.5f) ? 1.f : 0.f, (d1 > 0.5f) ? 1.f : 0.f);
                *(uint32_t*)(g_kb + (size_t)(row0 + 8) * DMODEL + col) =
                    pack2h((d2 > 0.5f) ? 1.f : 0.f, (d3 > 0.5f) ? 1.f : 0.f);
                // flag entries too close to the threshold for exact recompute
                if (fabsf(d0 - 0.5f) < EPS_K) {
                    int ix = atomicAdd(&g_nfix, 1);
                    if (ix < MAXFIX) g_fix[ix] = make_int2(row0, col);
                }
                if (fabsf(d1 - 0.5f) < EPS_K) {
                    int ix = atomicAdd(&g_nfix, 1);
                    if (ix < MAXFIX) g_fix[ix] = make_int2(row0, col + 1);
                }
                if (fabsf(d2 - 0.5f) < EPS_K) {
                    int ix = atomicAdd(&g_nfix, 1);
                    if (ix < MAXFIX) g_fix[ix] = make_int2(row0 + 8, col);
                }
                if (fabsf(d3 - 0.5f) < EPS_K) {
                    int ix = atomicAdd(&g_nfix, 1);
                    if (ix < MAXFIX) g_fix[ix] = make_int2(row0 + 8, col + 1);
                }
            } else if (mode == 2) {
                const int b  = row0 >> 11, tl = row0 & (TSEQ - 1);
                const int hh = col >> 6,  dd = col & (DHEAD - 1);
                const size_t base = ((size_t)(b * NHEAD + hh)) * DHEAD;
                g_vf[(base + dd) * TSEQ + tl]         = __float2half(d0);
                g_vf[(base + dd + 1) * TSEQ + tl]     = __float2half(d1);
                g_vf[(base + dd) * TSEQ + tl + 8]     = __float2half(d2);
                g_vf[(base + dd + 1) * TSEQ + tl + 8] = __float2half(d3);
            } else {
                float b0 = bias[col], b1 = bias[col + 1];
                *(float2*)(Cout + (size_t)row0 * DMODEL + col)       = make_float2(d0 + b0, d1 + b1);
                *(float2*)(Cout + (size_t)(row0 + 8) * DMODEL + col) = make_float2(d2 + b0, d3 + b1);
            }
        }
    }
}

// ---------------- fixup: exact fp32 recompute of flagged k entries ------------
// One warp per flagged (row, col): score = sum_d mix(x)[d] * Wk[col][d] in fp32.
__global__ void fixup_k(const float* __restrict__ X, const float* __restrict__ Wk)
{
    const int lane = threadIdx.x & 31;
    const int gw   = (blockIdx.x * blockDim.x + threadIdx.x) >> 5;
    const int nw   = (gridDim.x * blockDim.x) >> 5;
    const int n    = min(g_nfix, MAXFIX);
    for (int i = gw; i < n; i += nw) {
        const int row = g_fix[i].x, col = g_fix[i].y;
        const bool hasp = (row & (TSEQ - 1)) != 0;
        const float* xr = X + (size_t)row * DMODEL;
        const float* xp = xr - DMODEL;
        const float* w  = Wk + (size_t)col * DMODEL;
        float acc = 0.f;
        for (int d = lane; d < DMODEL; d += 32) {
            float m = g_m[1][d];
            float a = m * xr[d] + (1.f - m) * (hasp ? xp[d] : 0.f);
            acc = fmaf(a, w[d], acc);
        }
        #pragma unroll
        for (int s = 16; s > 0; s >>= 1)
            acc += __shfl_xor_sync(0xffffffffu, acc, s);
        if (lane == 0)
            g_kb[(size_t)row * DMODEL + col] = __float2half((acc > 0.5f) ? 1.f : 0.f);
    }
}

// ---------------- flash attention: no online softmax (bounded scores) ----------
#define KS 72
#define VS 40
__global__ __launch_bounds__(256)
void attn_f16()
{
    __shared__ __align__(16) __half sKb[2][32 * KS];
    __shared__ __align__(16) __half sVf[2][64 * VS];

    const int tid = threadIdx.x, warp = tid >> 5, lane = tid & 31;
    const int qr = lane >> 2, qc = lane & 3;
    const int b = blockIdx.z, h = blockIdx.y;
    const int qb = blockIdx.x * 128 + warp * 16;

    const int kkey = tid >> 3, kdg = (tid & 7) * 8;
    const int vd = tid >> 2,   vkg = (tid & 3) * 8;
    const size_t vbase = ((size_t)(b * NHEAD + h)) * DHEAD * TSEQ;
    const __half* gK  = g_kb + (size_t)(b * TSEQ + kkey) * DMODEL + h * DHEAD + kdg;
    const __half* gVf = g_vf + vbase + (size_t)vd * TSEQ + vkg;
    const uint32_t sKa  = smem_u32(sKb) + (kkey * KS + kdg) * 2;
    const uint32_t sVfa = smem_u32(sVf) + (vd * VS + vkg) * 2;
    const uint32_t KBUF = 32 * KS * 2, VBUF = 64 * VS * 2;

    uint32_t qf[4][4];
    {
        const size_t r0 = (size_t)(b * TSEQ + qb + qr) * DMODEL + h * DHEAD;
        const size_t r1 = r0 + (size_t)8 * DMODEL;
        #pragma unroll
        for (int kc = 0; kc < 4; kc++) {
            const int cc = kc * 16 + 2 * qc;
            qf[kc][0] = U32(g_qs + r0 + cc);     qf[kc][1] = U32(g_qs + r1 + cc);
            qf[kc][2] = U32(g_qs + r0 + cc + 8); qf[kc][3] = U32(g_qs + r1 + cc + 8);
        }
    }

    float o[8][4];
    #pragma unroll
    for (int nd = 0; nd < 8; nd++)
        #pragma unroll
        for (int e = 0; e < 4; e++) o[nd][e] = 0.f;
    float l0 = 0.f, l1 = 0.f;

    CP16(sKa, gK);
    CP16(sVfa, gVf);
    CPCOMMIT();

    int buf = 0;
    for (int kt = 0; kt < TSEQ; kt += 32) {
        CPWAIT0();
        __syncthreads();
        if (kt + 32 < TSEQ) {
            const int nb = buf ^ 1;
            CP16(sKa + nb * KBUF, gK + (kt + 32) * DMODEL);
            CP16(sVfa + nb * VBUF, gVf + kt + 32);
            CPCOMMIT();
        }
        const __half* Kb = sKb[buf];
        const __half* Vf = sVf[buf];

        float s[4][4];
        #pragma unroll
        for (int nt = 0; nt < 4; nt++) {
            #pragma unroll
            for (int e = 0; e < 4; e++) s[nt][e] = 0.f;
            #pragma unroll
            for (int kc = 0; kc < 4; kc++) {
                const int off = (nt * 8 + qr) * KS + kc * 16 + 2 * qc;
                uint32_t b0 = U32(Kb + off), b1 = U32(Kb + off + 8);
                MMA_F16(s[nt], qf[kc][0], qf[kc][1], qf[kc][2], qf[kc][3], b0, b1);
            }
        }

        #pragma unroll
        for (int nt = 0; nt < 4; nt++) {
            s[nt][0] = exps4(s[nt][0]);
            s[nt][1] = exps4(s[nt][1]);
            s[nt][2] = exps4(s[nt][2]);
            s[nt][3] = exps4(s[nt][3]);
            l0 += s[nt][0] + s[nt][1];
            l1 += s[nt][2] + s[nt][3];
        }

        #pragma unroll
        for (int kc = 0; kc < 2; kc++) {
            uint32_t a0 = pack2h(s[2*kc][0],     s[2*kc][1]);
            uint32_t a1 = pack2h(s[2*kc][2],     s[2*kc][3]);
            uint32_t a2 = pack2h(s[2*kc + 1][0], s[2*kc + 1][1]);
            uint32_t a3 = pack2h(s[2*kc + 1][2], s[2*kc + 1][3]);
            const int k0 = kc * 16 + 2 * qc;
            #pragma unroll
            for (int nd = 0; nd < 8; nd++) {
                const int off = (nd * 8 + qr) * VS + k0;
                uint32_t bh0 = U32(Vf + off), bh1 = U32(Vf + off + 8);
                MMA_F16(o[nd], a0, a1, a2, a3, bh0, bh1);
            }
        }
        buf ^= 1;
    }

    l0 += __shfl_xor_sync(0xffffffffu, l0, 1);
    l0 += __shfl_xor_sync(0xffffffffu, l0, 2);
    l1 += __shfl_xor_sync(0xffffffffu, l1, 1);
    l1 += __shfl_xor_sync(0xffffffffu, l1, 2);

    const float inv0 = 1.f / l0, inv1 = 1.f / l1;
    const size_t r0 = (size_t)(b * TSEQ + qb + qr) * DMODEL + h * DHEAD;
    const size_t r1 = r0 + (size_t)8 * DMODEL;
    #pragma unroll
    for (int nd = 0; nd < 8; nd++) {
        const int cc = nd * 8 + 2 * qc;
        float2 gt0 = *(const float2*)(g_gate + r0 + cc);
        float2 gt1 = *(const float2*)(g_gate + r1 + cc);
        *(uint32_t*)(g_ah[0] + r0 + cc) =
            pack2h(o[nd][0] * inv0 * gt0.x, o[nd][1] * inv0 * gt0.y);
        *(uint32_t*)(g_ah[0] + r1 + cc) =
            pack2h(o[nd][2] * inv1 * gt1.x, o[nd][3] * inv1 * gt1.y);
    }
}

// ---------------- launch (only harness pointers cross the boundary) ----------
extern "C" void kernel_launch(void* const* d_in, const int* in_sizes, int n_in,
                              void* d_out, int out_size)
{
    const float* x   = (const float*)d_in[0];
    const int*   tok = (const int*)  d_in[1];
    const float* Wr  = (const float*)d_in[2];
    const float* Wk  = (const float*)d_in[3];
    const float* Wv  = (const float*)d_in[4];
    const float* Wo  = (const float*)d_in[5];
    const float* bo  = (const float*)d_in[6];
    const float* tmk = (const float*)d_in[7];
    const float* tmv = (const float*)d_in[8];
    const float* tmr = (const float*)d_in[9];
    float* out = (float*)d_out;

    zero_cnt_kernel<<<(VOCAB + 255) / 256, 256>>>();
    hist_kernel<<<BT / 256, 256>>>(tok);
    topk_gains_kernel<<<1, 256>>>(tmr, tmk, tmv);

    split_w_all<<<(DMODEL * DMODEL) / 256, 256>>>(Wr, Wk, Wv, Wo);
    prep_x012<<<(BT * DMODEL) / 256, 256>>>(x);

    gemm_1t<<<dim3(DMODEL / 128, BT / 128, 3), 256>>>(0, nullptr, nullptr);   // r, k, v
    fixup_k<<<296, 256>>>(x, Wk);                                             // exact near-threshold k

    attn_f16<<<dim3(TSEQ / 128, NHEAD, BATCH), 256>>>();

    gemm_1t<<<dim3(DMODEL / 128, BT / 128, 1), 256>>>(3, bo, out);            // output
}